// round 7
// baseline (speedup 1.0000x reference)
#include <cuda_runtime.h>
#include <math.h>

#define T_TOK   2048
#define H_DIM   128
#define H4_DIM  512
#define N_NODES 256
#define TB      8

// Scratch (allocation-free per harness rules)
__device__ int   g_count[N_NODES];
__device__ int   g_tokens[N_NODES * T_TOK];
__device__ float g_h[T_TOK * H4_DIM];   // 4 MB intermediate (L2-resident)

__global__ void zero_counts_kernel() {
    g_count[threadIdx.x] = 0;
}

__global__ void build_lists_kernel(const int* __restrict__ node_ind) {
    int t = blockIdx.x * blockDim.x + threadIdx.x;
    if (t < T_TOK) {
        int n = node_ind[t];
        int pos = atomicAdd(&g_count[n], 1);
        g_tokens[n * T_TOK + pos] = t;
    }
}

__device__ __forceinline__ float gelu_exact(float v) {
    return 0.5f * v * (1.0f + erff(v * 0.70710678118654752f));
}

// ============================================================================
// Layer 1: grid = N_NODES*8. CTA (n,q) owns rows [q*64, q*64+64) of W1[n].
// 256 threads / 8 warps. Warp w owns rows w*8 + it*4 + g (it=0..1, g=0..3).
// Lane = (g<<3)|c : row-dot split over 8 lanes (c), 4 row-slots (g) in
// parallel. Activation LDS.128 has only 8 distinct addresses (c) -> 1
// wavefront, reused across it=0,1 (hoisted). 3-step shuffle reduce over c.
// ============================================================================
__global__ __launch_bounds__(256)
void layer1_kernel(const float* __restrict__ x,
                   const float* __restrict__ W1,
                   const float* __restrict__ b1) {
    __shared__ float xs[TB][H_DIM];   // 4 KB
    __shared__ int   stoks[TB];

    const int b = blockIdx.x;
    const int n = b >> 3;
    const int q = b & 7;
    const int nt_total = g_count[n];
    if (nt_total == 0) return;

    const int tid  = threadIdx.x;
    const int w    = tid >> 5;
    const int lane = tid & 31;
    const int g    = lane >> 3;   // row slot 0..3
    const int c    = lane & 7;    // k-chunk 0..7 (16 floats per lane per row)

    const float* W1c = W1 + (size_t)n * H4_DIM * H_DIM + (size_t)q * 64 * H_DIM;
    const float* b1c = b1 + n * H4_DIM + q * 64;

    // Weights in regs: 2 rows x 4 float4 = 32 floats/thread
    float4 wv[2][4];
    float  bias[2];
    #pragma unroll
    for (int it = 0; it < 2; it++) {
        const int rr = w * 8 + it * 4 + g;
        const float4* wr = (const float4*)(W1c + (size_t)rr * H_DIM);
        #pragma unroll
        for (int j = 0; j < 4; j++) wv[it][j] = wr[c * 4 + j];
        bias[it] = b1c[rr];
    }

    for (int base = 0; base < nt_total; base += TB) {
        const int nt = min(TB, nt_total - base);

        __syncthreads();
        if (tid < nt) stoks[tid] = g_tokens[n * T_TOK + base + tid];
        __syncthreads();
        if (tid < nt * 32) {
            int tk = tid >> 5;
            int l4 = tid & 31;
            ((float4*)xs[tk])[l4] =
                ((const float4*)(x + (size_t)stoks[tk] * H_DIM))[l4];
        }
        __syncthreads();

        float acc[2][TB];
        #pragma unroll
        for (int it = 0; it < 2; it++)
            #pragma unroll
            for (int t = 0; t < TB; t++) acc[it][t] = 0.f;

        #pragma unroll
        for (int t = 0; t < TB; t++) {
            if (t < nt) {
                #pragma unroll
                for (int j = 0; j < 4; j++) {
                    float4 xv = ((const float4*)xs[t])[c * 4 + j];
                    #pragma unroll
                    for (int it = 0; it < 2; it++) {
                        acc[it][t] += wv[it][j].x * xv.x + wv[it][j].y * xv.y
                                    + wv[it][j].z * xv.z + wv[it][j].w * xv.w;
                    }
                }
            }
        }

        #pragma unroll
        for (int it = 0; it < 2; it++) {
            const int rr = w * 8 + it * 4 + g;
            #pragma unroll
            for (int t = 0; t < TB; t++) {
                if (t < nt) {
                    float v = acc[it][t];
                    v += __shfl_xor_sync(0xffffffffu, v, 4);
                    v += __shfl_xor_sync(0xffffffffu, v, 2);
                    v += __shfl_xor_sync(0xffffffffu, v, 1);
                    if (c == 0)
                        g_h[(size_t)stoks[t] * H4_DIM + q * 64 + rr] =
                            gelu_exact(v + bias[it]);
                }
            }
        }
    }
}

// ============================================================================
// Layer 2: grid = N_NODES*8. CTA (n,q) owns rows [q*16, q*16+16) of W2[n].
// 256 threads / 8 warps. Warp w owns rows w*2 + g (g=0..1).
// Lane = (g<<4)|c : row-dot split over 16 lanes (c), 2 slots in parallel.
// Activation LDS.128 has 16 distinct addresses -> 2 wavefronts.
// 4-step shuffle reduce over c.
// ============================================================================
__global__ __launch_bounds__(256)
void layer2_kernel(const float* __restrict__ W2,
                   const float* __restrict__ b2,
                   float* __restrict__ out) {
    __shared__ float hs[TB][H4_DIM];   // 16 KB
    __shared__ int   stoks[TB];

    const int b = blockIdx.x;
    const int n = b >> 3;
    const int q = b & 7;
    const int nt_total = g_count[n];
    if (nt_total == 0) return;

    const int tid  = threadIdx.x;
    const int w    = tid >> 5;
    const int lane = tid & 31;
    const int g    = lane >> 4;   // row slot 0..1
    const int c    = lane & 15;   // k-chunk 0..15 (32 floats per lane)

    const int rr = q * 16 + w * 2 + g;           // output column within node
    const float* W2r = W2 + (size_t)n * H_DIM * H4_DIM + (size_t)rr * H4_DIM;

    // Weights in regs: 8 float4 = 32 floats/thread (k = c*32 + j*4)
    float4 wv[8];
    #pragma unroll
    for (int j = 0; j < 8; j++) wv[j] = ((const float4*)W2r)[c * 8 + j];
    const float bias = b2[n * H_DIM + rr];

    for (int base = 0; base < nt_total; base += TB) {
        const int nt = min(TB, nt_total - base);

        __syncthreads();
        if (tid < nt) stoks[tid] = g_tokens[n * T_TOK + base + tid];
        __syncthreads();
        // Stage h rows: nt*128 float4; 256 threads -> up to 4 each
        #pragma unroll
        for (int k = 0; k < 4; k++) {
            int idx = tid + k * 256;
            int tk = idx >> 7;
            int l4 = idx & 127;
            if (tk < nt)
                ((float4*)hs[tk])[l4] =
                    ((const float4*)(g_h + (size_t)stoks[tk] * H4_DIM))[l4];
        }
        __syncthreads();

        float acc[TB];
        #pragma unroll
        for (int t = 0; t < TB; t++) acc[t] = 0.f;

        #pragma unroll
        for (int t = 0; t < TB; t++) {
            if (t < nt) {
                #pragma unroll
                for (int j = 0; j < 8; j++) {
                    float4 hv = ((const float4*)hs[t])[c * 8 + j];
                    acc[t] += wv[j].x * hv.x + wv[j].y * hv.y
                            + wv[j].z * hv.z + wv[j].w * hv.w;
                }
            }
        }

        #pragma unroll
        for (int t = 0; t < TB; t++) {
            if (t < nt) {
                float v = acc[t];
                v += __shfl_xor_sync(0xffffffffu, v, 8);
                v += __shfl_xor_sync(0xffffffffu, v, 4);
                v += __shfl_xor_sync(0xffffffffu, v, 2);
                v += __shfl_xor_sync(0xffffffffu, v, 1);
                if (c == 0)
                    out[(size_t)stoks[t] * H_DIM + rr] = v + bias;
            }
        }
    }
}

extern "C" void kernel_launch(void* const* d_in, const int* in_sizes, int n_in,
                              void* d_out, int out_size) {
    const float* x        = (const float*)d_in[0];
    const int*   node_ind = (const int*)  d_in[1];
    const float* W1       = (const float*)d_in[2];
    const float* b1       = (const float*)d_in[3];
    const float* W2       = (const float*)d_in[4];
    const float* b2       = (const float*)d_in[5];
    float*       out      = (float*)d_out;

    zero_counts_kernel<<<1, N_NODES>>>();
    build_lists_kernel<<<(T_TOK + 255) / 256, 256>>>(node_ind);
    layer1_kernel<<<N_NODES * 8, 256>>>(x, W1, b1);
    layer2_kernel<<<N_NODES * 8, 256>>>(W2, b2, out);
}

// round 8
// speedup vs baseline: 2.6524x; 2.6524x over previous
#include <cuda_runtime.h>
#include <math.h>

#define T_TOK   2048
#define H_DIM   128
#define H4_DIM  512
#define N_NODES 256
#define TB      8    // layer1 token chunk
#define TB2     4    // layer2 token chunk

// Scratch (allocation-free per harness rules)
__device__ int   g_count[N_NODES];
__device__ int   g_tokens[N_NODES * T_TOK];
__device__ float g_h[T_TOK * H4_DIM];   // 4 MB intermediate (L2-resident)

__global__ void zero_counts_kernel() {
    g_count[threadIdx.x] = 0;
}

__global__ void build_lists_kernel(const int* __restrict__ node_ind) {
    int t = blockIdx.x * blockDim.x + threadIdx.x;
    if (t < T_TOK) {
        int n = node_ind[t];
        int pos = atomicAdd(&g_count[n], 1);
        g_tokens[n * T_TOK + pos] = t;
    }
}

__device__ __forceinline__ float gelu_exact(float v) {
    return 0.5f * v * (1.0f + erff(v * 0.70710678118654752f));
}

// ============================================================================
// Layer 1: grid = N_NODES*8. CTA (n,q) owns rows [q*64, q*64+64) of W1[n].
// 256 threads / 8 warps. Warp w owns rows w*8 + it*4 + g (it=0..1, g=0..3).
// Lane = (g<<3)|c. Activation float4 index [j*8+c]: lanes c consecutive
// (128B = 1 wavefront), g groups broadcast. xv SHARED across both it rows.
// ============================================================================
__global__ __launch_bounds__(256, 3)
void layer1_kernel(const float* __restrict__ x,
                   const float* __restrict__ W1,
                   const float* __restrict__ b1) {
    __shared__ float xs[TB][H_DIM];   // 4 KB
    __shared__ int   stoks[TB];

    const int b = blockIdx.x;
    const int n = b >> 3;
    const int q = b & 7;

    const int tid  = threadIdx.x;
    const int w    = tid >> 5;
    const int lane = tid & 31;
    const int g    = lane >> 3;   // row slot 0..3 (broadcast group)
    const int c    = lane & 7;    // k-chunk 0..7

    const float* W1c = W1 + (size_t)n * H4_DIM * H_DIM + (size_t)q * 64 * H_DIM;
    const float* b1c = b1 + n * H4_DIM + q * 64;

    // Weights in regs: 2 rows x 4 float4 = 32 floats/thread
    float4 wv[2][4];
    float  bias[2];
    #pragma unroll
    for (int it = 0; it < 2; it++) {
        const int rr = w * 8 + it * 4 + g;
        const float4* wr = (const float4*)(W1c + (size_t)rr * H_DIM);
        #pragma unroll
        for (int j = 0; j < 4; j++) wv[it][j] = wr[j * 8 + c];
        bias[it] = b1c[rr];
    }

    const int nt_total = g_count[n];

    for (int base = 0; base < nt_total; base += TB) {
        const int nt = min(TB, nt_total - base);

        __syncthreads();
        if (tid < nt) stoks[tid] = g_tokens[n * T_TOK + base + tid];
        __syncthreads();
        if (tid < nt * 32) {
            int tk = tid >> 5;
            int l4 = tid & 31;
            ((float4*)xs[tk])[l4] =
                ((const float4*)(x + (size_t)stoks[tk] * H_DIM))[l4];
        }
        __syncthreads();

        float acc[2][TB];
        #pragma unroll
        for (int it = 0; it < 2; it++)
            #pragma unroll
            for (int t = 0; t < TB; t++) acc[it][t] = 0.f;

        #pragma unroll
        for (int t = 0; t < TB; t++) {
            if (t < nt) {
                #pragma unroll
                for (int j = 0; j < 4; j++) {
                    float4 xv = ((const float4*)xs[t])[j * 8 + c];  // shared by both rows
                    acc[0][t] += wv[0][j].x * xv.x + wv[0][j].y * xv.y
                               + wv[0][j].z * xv.z + wv[0][j].w * xv.w;
                    acc[1][t] += wv[1][j].x * xv.x + wv[1][j].y * xv.y
                               + wv[1][j].z * xv.z + wv[1][j].w * xv.w;
                }
            }
        }

        #pragma unroll
        for (int it = 0; it < 2; it++) {
            const int rr = w * 8 + it * 4 + g;
            #pragma unroll
            for (int t = 0; t < TB; t++) {
                if (t < nt) {
                    float v = acc[it][t];
                    v += __shfl_xor_sync(0xffffffffu, v, 4);
                    v += __shfl_xor_sync(0xffffffffu, v, 2);
                    v += __shfl_xor_sync(0xffffffffu, v, 1);
                    if (c == 0)
                        g_h[(size_t)stoks[t] * H4_DIM + q * 64 + rr] =
                            gelu_exact(v + bias[it]);
                }
            }
        }
    }
}

// ============================================================================
// Layer 2: grid = N_NODES*4. CTA (n,q) owns rows [q*32, q*32+32) of W2[n].
// 256 threads / 8 warps. Warp w owns 4 SEQUENTIAL rows w*4+it (it=0..3),
// 32-lane k-split, conflict-free [j*32+lane] layout. Each activation LDS.128
// is reused by 4 rows (weights in regs: wv[4][4] = 64 floats).
// ============================================================================
__global__ __launch_bounds__(256, 2)
void layer2_kernel(const float* __restrict__ W2,
                   const float* __restrict__ b2,
                   float* __restrict__ out) {
    __shared__ float hs[TB2][H4_DIM];   // 8 KB
    __shared__ int   stoks[TB2];

    const int b = blockIdx.x;
    const int n = b >> 2;
    const int q = b & 3;

    const int tid  = threadIdx.x;
    const int w    = tid >> 5;
    const int lane = tid & 31;

    const float* W2c = W2 + (size_t)n * H_DIM * H4_DIM + (size_t)(q * 32) * H4_DIM;
    const float* b2c = b2 + n * H_DIM + q * 32;

    // Weights in regs: 4 rows x 4 float4 = 64 floats/thread
    float4 wv[4][4];
    float  bias[4];
    #pragma unroll
    for (int it = 0; it < 4; it++) {
        const int rr = w * 4 + it;
        const float4* wr = (const float4*)(W2c + (size_t)rr * H4_DIM);
        #pragma unroll
        for (int j = 0; j < 4; j++) wv[it][j] = wr[j * 32 + lane];
        bias[it] = b2c[rr];
    }

    const int nt_total = g_count[n];

    for (int base = 0; base < nt_total; base += TB2) {
        const int nt = min(TB2, nt_total - base);

        __syncthreads();
        if (tid < nt) stoks[tid] = g_tokens[n * T_TOK + base + tid];
        __syncthreads();
        // Stage h rows: nt*128 float4; 256 threads -> up to 2 each
        #pragma unroll
        for (int k = 0; k < 2; k++) {
            int idx = tid + k * 256;
            int tk = idx >> 7;
            int l4 = idx & 127;
            if (tk < nt)
                ((float4*)hs[tk])[l4] =
                    ((const float4*)(g_h + (size_t)stoks[tk] * H4_DIM))[l4];
        }
        __syncthreads();

        float acc[4][TB2];
        #pragma unroll
        for (int it = 0; it < 4; it++)
            #pragma unroll
            for (int t = 0; t < TB2; t++) acc[it][t] = 0.f;

        #pragma unroll
        for (int t = 0; t < TB2; t++) {
            if (t < nt) {
                #pragma unroll
                for (int j = 0; j < 4; j++) {
                    float4 hv = ((const float4*)hs[t])[j * 32 + lane];  // 1 load -> 4 rows
                    #pragma unroll
                    for (int it = 0; it < 4; it++) {
                        acc[it][t] += wv[it][j].x * hv.x + wv[it][j].y * hv.y
                                    + wv[it][j].z * hv.z + wv[it][j].w * hv.w;
                    }
                }
            }
        }

        #pragma unroll
        for (int it = 0; it < 4; it++) {
            const int rr = q * 32 + w * 4 + it;
            #pragma unroll
            for (int t = 0; t < TB2; t++) {
                if (t < nt) {
                    float v = acc[it][t];
                    #pragma unroll
                    for (int s = 16; s > 0; s >>= 1)
                        v += __shfl_xor_sync(0xffffffffu, v, s);
                    if (lane == 0)
                        out[(size_t)stoks[t] * H_DIM + rr] = v + bias[it];
                }
            }
        }
    }
}

extern "C" void kernel_launch(void* const* d_in, const int* in_sizes, int n_in,
                              void* d_out, int out_size) {
    const float* x        = (const float*)d_in[0];
    const int*   node_ind = (const int*)  d_in[1];
    const float* W1       = (const float*)d_in[2];
    const float* b1       = (const float*)d_in[3];
    const float* W2       = (const float*)d_in[4];
    const float* b2       = (const float*)d_in[5];
    float*       out      = (float*)d_out;

    zero_counts_kernel<<<1, N_NODES>>>();
    build_lists_kernel<<<(T_TOK + 255) / 256, 256>>>(node_ind);
    layer1_kernel<<<N_NODES * 8, 256>>>(x, W1, b1);
    layer2_kernel<<<N_NODES * 4, 256>>>(W2, b2, out);
}

// round 11
// speedup vs baseline: 2.9474x; 1.1112x over previous
#include <cuda_runtime.h>
#include <math.h>

#define T_TOK   2048
#define H_DIM   128
#define H4_DIM  512
#define N_NODES 256
#define TB      8    // tokens per chunk
#define NC      4    // token chunks in grid (covers 32 tokens; stride loop beyond)

// Scratch (allocation-free per harness rules)
__device__ int   g_count[N_NODES];
__device__ int   g_tokens[N_NODES * T_TOK];
__device__ float g_h[T_TOK * H4_DIM];   // 4 MB intermediate (L2-resident)

__global__ void zero_counts_kernel() {
    g_count[threadIdx.x] = 0;
}

__global__ void build_lists_kernel(const int* __restrict__ node_ind) {
    int t = blockIdx.x * blockDim.x + threadIdx.x;
    if (t < T_TOK) {
        int n = node_ind[t];
        int pos = atomicAdd(&g_count[n], 1);
        g_tokens[n * T_TOK + pos] = t;
    }
}

__device__ __forceinline__ float gelu_exact(float v) {
    return 0.5f * v * (1.0f + erff(v * 0.70710678118654752f));
}

// ============================================================================
// Layer 1: grid = N_NODES*8*NC. bid -> (n, q rows-of-64, tc token-chunk).
// 256 thr / 8 warps. Warp w owns rows w*8 + it*4 + g (it=0..1, g=0..3).
// lane=(g<<3)|c; activation float4 [j*8+c]: 16B lane stride -> 1 wavefront,
// broadcast across g, xv shared by both it rows. 3-step shuffle.
// Typical CTA: ONE pass (chunk), one latency chain.
// ============================================================================
__global__ __launch_bounds__(256, 3)
void layer1_kernel(const float* __restrict__ x,
                   const float* __restrict__ W1,
                   const float* __restrict__ b1) {
    __shared__ float xs[TB][H_DIM];   // 4 KB
    __shared__ int   stoks[TB];

    const int b  = blockIdx.x;
    const int tc = b & (NC - 1);
    const int q  = (b >> 2) & 7;
    const int n  = b >> 5;
    const int base0 = tc * TB;

    const int tid  = threadIdx.x;

    // Speculative token-id load (independent of count; address always valid)
    int spec_tok = 0;
    if (tid < TB) spec_tok = g_tokens[n * T_TOK + base0 + tid];
    const int nt_total = g_count[n];
    if (base0 >= nt_total) return;

    const int w    = tid >> 5;
    const int lane = tid & 31;
    const int g    = lane >> 3;   // row slot 0..3 (broadcast group)
    const int c    = lane & 7;    // k-chunk 0..7

    const float* W1c = W1 + (size_t)n * H4_DIM * H_DIM + (size_t)q * 64 * H_DIM;
    const float* b1c = b1 + n * H4_DIM + q * 64;

    // Weights in regs: 2 rows x 4 float4 = 32 floats/thread
    float4 wv[2][4];
    float  bias[2];
    #pragma unroll
    for (int it = 0; it < 2; it++) {
        const int rr = w * 8 + it * 4 + g;
        const float4* wr = (const float4*)(W1c + (size_t)rr * H_DIM);
        #pragma unroll
        for (int j = 0; j < 4; j++) wv[it][j] = wr[j * 8 + c];
        bias[it] = b1c[rr];
    }

    for (int base = base0; base < nt_total; base += NC * TB) {
        const int nt = min(TB, nt_total - base);

        __syncthreads();
        if (tid < nt)
            stoks[tid] = (base == base0) ? spec_tok
                                         : g_tokens[n * T_TOK + base + tid];
        __syncthreads();
        if (tid < nt * 32) {
            int tk = tid >> 5;
            int l4 = tid & 31;
            ((float4*)xs[tk])[l4] =
                ((const float4*)(x + (size_t)stoks[tk] * H_DIM))[l4];
        }
        __syncthreads();

        float acc[2][TB];
        #pragma unroll
        for (int it = 0; it < 2; it++)
            #pragma unroll
            for (int t = 0; t < TB; t++) acc[it][t] = 0.f;

        #pragma unroll
        for (int t = 0; t < TB; t++) {
            if (t < nt) {
                #pragma unroll
                for (int j = 0; j < 4; j++) {
                    float4 xv = ((const float4*)xs[t])[j * 8 + c];  // shared by both rows
                    acc[0][t] += wv[0][j].x * xv.x + wv[0][j].y * xv.y
                               + wv[0][j].z * xv.z + wv[0][j].w * xv.w;
                    acc[1][t] += wv[1][j].x * xv.x + wv[1][j].y * xv.y
                               + wv[1][j].z * xv.z + wv[1][j].w * xv.w;
                }
            }
        }

        #pragma unroll
        for (int it = 0; it < 2; it++) {
            const int rr = w * 8 + it * 4 + g;
            #pragma unroll
            for (int t = 0; t < TB; t++) {
                if (t < nt) {
                    float v = acc[it][t];
                    v += __shfl_xor_sync(0xffffffffu, v, 4);
                    v += __shfl_xor_sync(0xffffffffu, v, 2);
                    v += __shfl_xor_sync(0xffffffffu, v, 1);
                    if (c == 0)
                        g_h[(size_t)stoks[t] * H4_DIM + q * 64 + rr] =
                            gelu_exact(v + bias[it]);
                }
            }
        }
    }
}

// ============================================================================
// Layer 2: grid = N_NODES*8*NC. bid -> (n, q rows-of-16, tc).
// 256 thr / 8 warps. Warp w owns rows q*16 + w*2 + g (g = lane>>4).
// 16-lane k-split with INTERLEAVED ownership: lane c owns float4s [j*16+c]
// (16B lane stride -> conflict-free, 2 wavefronts, broadcast across g).
// 4-step shuffle within the 16-lane group.
// ============================================================================
__global__ __launch_bounds__(256, 3)
void layer2_kernel(const float* __restrict__ W2,
                   const float* __restrict__ b2,
                   float* __restrict__ out) {
    __shared__ float hs[TB][H4_DIM];   // 16 KB
    __shared__ int   stoks[TB];

    const int b  = blockIdx.x;
    const int tc = b & (NC - 1);
    const int q  = (b >> 2) & 7;
    const int n  = b >> 5;
    const int base0 = tc * TB;

    const int tid  = threadIdx.x;

    int spec_tok = 0;
    if (tid < TB) spec_tok = g_tokens[n * T_TOK + base0 + tid];
    const int nt_total = g_count[n];
    if (base0 >= nt_total) return;

    const int w    = tid >> 5;
    const int lane = tid & 31;
    const int g    = lane >> 4;   // row slot 0..1
    const int c    = lane & 15;   // k-chunk 0..15

    const int rr = q * 16 + w * 2 + g;
    const float* W2r = W2 + (size_t)n * H_DIM * H4_DIM + (size_t)rr * H4_DIM;

    // Weights in regs: 8 float4 = 32 floats/thread, k4-index = j*16 + c
    float4 wv[8];
    #pragma unroll
    for (int j = 0; j < 8; j++) wv[j] = ((const float4*)W2r)[j * 16 + c];
    const float bias = b2[n * H_DIM + rr];

    for (int base = base0; base < nt_total; base += NC * TB) {
        const int nt = min(TB, nt_total - base);

        __syncthreads();
        if (tid < nt)
            stoks[tid] = (base == base0) ? spec_tok
                                         : g_tokens[n * T_TOK + base + tid];
        __syncthreads();
        // Stage h rows: nt*128 float4; 256 threads -> up to 4 each
        #pragma unroll
        for (int k = 0; k < 4; k++) {
            int idx = tid + k * 256;
            int tk = idx >> 7;
            int l4 = idx & 127;
            if (tk < nt)
                ((float4*)hs[tk])[l4] =
                    ((const float4*)(g_h + (size_t)stoks[tk] * H4_DIM))[l4];
        }
        __syncthreads();

        float acc[TB];
        #pragma unroll
        for (int t = 0; t < TB; t++) acc[t] = 0.f;

        #pragma unroll
        for (int t = 0; t < TB; t++) {
            if (t < nt) {
                #pragma unroll
                for (int j = 0; j < 8; j++) {
                    float4 hv = ((const float4*)hs[t])[j * 16 + c];
                    acc[t] += wv[j].x * hv.x + wv[j].y * hv.y
                            + wv[j].z * hv.z + wv[j].w * hv.w;
                }
            }
        }

        #pragma unroll
        for (int t = 0; t < TB; t++) {
            if (t < nt) {
                float v = acc[t];
                v += __shfl_xor_sync(0xffffffffu, v, 8);
                v += __shfl_xor_sync(0xffffffffu, v, 4);
                v += __shfl_xor_sync(0xffffffffu, v, 2);
                v += __shfl_xor_sync(0xffffffffu, v, 1);
                if (c == 0)
                    out[(size_t)stoks[t] * H_DIM + rr] = v + bias;
            }
        }
    }
}

extern "C" void kernel_launch(void* const* d_in, const int* in_sizes, int n_in,
                              void* d_out, int out_size) {
    const float* x        = (const float*)d_in[0];
    const int*   node_ind = (const int*)  d_in[1];
    const float* W1       = (const float*)d_in[2];
    const float* b1       = (const float*)d_in[3];
    const float* W2       = (const float*)d_in[4];
    const float* b2       = (const float*)d_in[5];
    float*       out      = (float*)d_out;

    zero_counts_kernel<<<1, N_NODES>>>();
    build_lists_kernel<<<(T_TOK + 255) / 256, 256>>>(node_ind);
    layer1_kernel<<<N_NODES * 8 * NC, 256>>>(x, W1, b1);
    layer2_kernel<<<N_NODES * 8 * NC, 256>>>(W2, b2, out);
}

// round 12
// speedup vs baseline: 3.8997x; 1.3231x over previous
#include <cuda_runtime.h>
#include <math.h>

#define T_TOK   2048
#define H_DIM   128
#define H4_DIM  512
#define N_NODES 256
#define TB      8    // tokens per chunk
#define NC      4    // token chunks in grid (covers 32 tokens; stride loop beyond)

// Scratch (allocation-free per harness rules)
__device__ int   g_count[N_NODES];
__device__ int   g_tokens[N_NODES * T_TOK];
__device__ float g_h[T_TOK * H4_DIM];   // 4 MB intermediate (L2-resident)

// Single-launch prep: 1024 threads, smem counters, 2 tokens/thread.
__global__ void prep_kernel(const int* __restrict__ node_ind) {
    __shared__ int scnt[N_NODES];
    const int tid = threadIdx.x;
    if (tid < N_NODES) scnt[tid] = 0;
    __syncthreads();
    #pragma unroll
    for (int t = tid; t < T_TOK; t += 1024) {
        int n = node_ind[t];
        int pos = atomicAdd(&scnt[n], 1);
        g_tokens[n * T_TOK + pos] = t;
    }
    __syncthreads();
    if (tid < N_NODES) g_count[tid] = scnt[tid];
}

__device__ __forceinline__ float gelu_exact(float v) {
    return 0.5f * v * (1.0f + erff(v * 0.70710678118654752f));
}

// ============================================================================
// Layer 1: grid = N_NODES*8*NC. bid -> (n, q rows-of-64, tc token-chunk).
// 256 thr / 8 warps. Warp w owns rows w*8 + it*4 + g (it=0..1, g=0..3).
// lane=(g<<3)|c; activation float4 [j*8+c]: 1 wavefront (broadcast over g),
// xv shared by both it rows. Distributing butterfly: after 7 shfl, lane c
// holds token c's full sum -> gelu ONCE per lane, multi-lane STG.
// ============================================================================
__global__ __launch_bounds__(256, 3)
void layer1_kernel(const float* __restrict__ x,
                   const float* __restrict__ W1,
                   const float* __restrict__ b1) {
    __shared__ float xs[TB][H_DIM];   // 4 KB
    __shared__ int   stoks[TB];

    const int b  = blockIdx.x;
    const int tc = b & (NC - 1);
    const int q  = (b >> 2) & 7;
    const int n  = b >> 5;
    const int base0 = tc * TB;

    const int tid = threadIdx.x;

    // Speculative token-id load (independent of count; address always valid)
    int spec_tok = 0;
    if (tid < TB) spec_tok = g_tokens[n * T_TOK + base0 + tid];
    const int nt_total = g_count[n];
    if (base0 >= nt_total) return;

    const int w    = tid >> 5;
    const int lane = tid & 31;
    const int g    = lane >> 3;   // row slot 0..3 (broadcast group)
    const int c    = lane & 7;    // k-chunk 0..7

    const float* W1c = W1 + (size_t)n * H4_DIM * H_DIM + (size_t)q * 64 * H_DIM;
    const float* b1c = b1 + n * H4_DIM + q * 64;

    float4 wv[2][4];
    float  bias[2];
    #pragma unroll
    for (int it = 0; it < 2; it++) {
        const int rr = w * 8 + it * 4 + g;
        const float4* wr = (const float4*)(W1c + (size_t)rr * H_DIM);
        #pragma unroll
        for (int j = 0; j < 4; j++) wv[it][j] = wr[j * 8 + c];
        bias[it] = b1c[rr];
    }

    for (int base = base0; base < nt_total; base += NC * TB) {
        const int nt = min(TB, nt_total - base);

        __syncthreads();
        if (tid < nt)
            stoks[tid] = (base == base0) ? spec_tok
                                         : g_tokens[n * T_TOK + base + tid];
        __syncthreads();
        if (tid < nt * 32) {
            int tk = tid >> 5;
            int l4 = tid & 31;
            ((float4*)xs[tk])[l4] =
                ((const float4*)(x + (size_t)stoks[tk] * H_DIM))[l4];
        }
        __syncthreads();

        float acc[2][TB];
        #pragma unroll
        for (int it = 0; it < 2; it++)
            #pragma unroll
            for (int t = 0; t < TB; t++) acc[it][t] = 0.f;

        #pragma unroll
        for (int t = 0; t < TB; t++) {
            if (t < nt) {
                #pragma unroll
                for (int j = 0; j < 4; j++) {
                    float4 xv = ((const float4*)xs[t])[j * 8 + c];
                    acc[0][t] += wv[0][j].x * xv.x + wv[0][j].y * xv.y
                               + wv[0][j].z * xv.z + wv[0][j].w * xv.w;
                    acc[1][t] += wv[1][j].x * xv.x + wv[1][j].y * xv.y
                               + wv[1][j].z * xv.z + wv[1][j].w * xv.w;
                }
            }
        }

        // Distributing butterfly over the 8-lane group: lane c ends with
        // token (c&7)'s full sum. Token bit for stage s: set iff (c&s).
        #pragma unroll
        for (int it = 0; it < 2; it++) {
            float a0 = acc[it][0], a1 = acc[it][1], a2 = acc[it][2], a3 = acc[it][3];
            float a4 = acc[it][4], a5 = acc[it][5], a6 = acc[it][6], a7 = acc[it][7];
            // s=4
            {
                float s0 = (c & 4) ? a0 : a4, s1 = (c & 4) ? a1 : a5;
                float s2 = (c & 4) ? a2 : a6, s3 = (c & 4) ? a3 : a7;
                float r0 = __shfl_xor_sync(0xffffffffu, s0, 4);
                float r1 = __shfl_xor_sync(0xffffffffu, s1, 4);
                float r2 = __shfl_xor_sync(0xffffffffu, s2, 4);
                float r3 = __shfl_xor_sync(0xffffffffu, s3, 4);
                a0 = ((c & 4) ? a4 : a0) + r0;
                a1 = ((c & 4) ? a5 : a1) + r1;
                a2 = ((c & 4) ? a6 : a2) + r2;
                a3 = ((c & 4) ? a7 : a3) + r3;
            }
            // s=2
            {
                float s0 = (c & 2) ? a0 : a2, s1 = (c & 2) ? a1 : a3;
                float r0 = __shfl_xor_sync(0xffffffffu, s0, 2);
                float r1 = __shfl_xor_sync(0xffffffffu, s1, 2);
                a0 = ((c & 2) ? a2 : a0) + r0;
                a1 = ((c & 2) ? a3 : a1) + r1;
            }
            // s=1
            {
                float s0 = (c & 1) ? a0 : a1;
                float r0 = __shfl_xor_sync(0xffffffffu, s0, 1);
                a0 = ((c & 1) ? a1 : a0) + r0;
            }
            const int tok = c;                       // token index = c&7
            const int rr  = w * 8 + it * 4 + g;
            float v = gelu_exact(a0 + bias[it]);     // once per lane
            if (tok < nt)
                g_h[(size_t)stoks[tok] * H4_DIM + q * 64 + rr] = v;
        }
    }
}

// ============================================================================
// Layer 2: grid = N_NODES*4*NC. bid -> (n, q rows-of-32, tc).
// 256 thr / 8 warps. Warp w owns 4 SEQUENTIAL rows q*32 + w*4 + it.
// Full 32-lane k-split [j*32+lane] (conflict-free); each LDS.128 feeds 4 rows
// (16 FFMA). Tokens processed in 2 halves of 4 to bound regs (acc[4][4]).
// Distributing butterfly: lane bits {16,8} pick the token; 4-lane groups store.
// ============================================================================
__global__ __launch_bounds__(256, 2)
void layer2_kernel(const float* __restrict__ W2,
                   const float* __restrict__ b2,
                   float* __restrict__ out) {
    __shared__ float hs[TB][H4_DIM];   // 16 KB
    __shared__ int   stoks[TB];

    const int b  = blockIdx.x;
    const int tc = b & (NC - 1);
    const int q  = (b >> 2) & 3;
    const int n  = b >> 4;
    const int base0 = tc * TB;

    const int tid = threadIdx.x;

    int spec_tok = 0;
    if (tid < TB) spec_tok = g_tokens[n * T_TOK + base0 + tid];
    const int nt_total = g_count[n];
    if (base0 >= nt_total) return;

    const int w    = tid >> 5;
    const int lane = tid & 31;

    const int row0 = q * 32 + w * 4;
    const float* W2c = W2 + (size_t)n * H_DIM * H4_DIM + (size_t)row0 * H4_DIM;

    // Weights in regs: 4 rows x 4 float4 = 64 floats/thread
    float4 wv[4][4];
    float  bias[4];
    #pragma unroll
    for (int it = 0; it < 4; it++) {
        const float4* wr = (const float4*)(W2c + (size_t)it * H4_DIM);
        #pragma unroll
        for (int j = 0; j < 4; j++) wv[it][j] = wr[j * 32 + lane];
        bias[it] = b2[n * H_DIM + row0 + it];
    }

    for (int base = base0; base < nt_total; base += NC * TB) {
        const int nt = min(TB, nt_total - base);

        __syncthreads();
        if (tid < nt)
            stoks[tid] = (base == base0) ? spec_tok
                                         : g_tokens[n * T_TOK + base + tid];
        __syncthreads();
        // Stage h rows: nt*128 float4; 256 threads -> up to 4 each
        #pragma unroll
        for (int k = 0; k < 4; k++) {
            int idx = tid + k * 256;
            int tk = idx >> 7;
            int l4 = idx & 127;
            if (tk < nt)
                ((float4*)hs[tk])[l4] =
                    ((const float4*)(g_h + (size_t)stoks[tk] * H4_DIM))[l4];
        }
        __syncthreads();

        #pragma unroll
        for (int h2 = 0; h2 < 2; h2++) {
            float acc[4][4];
            #pragma unroll
            for (int it = 0; it < 4; it++)
                #pragma unroll
                for (int tl = 0; tl < 4; tl++) acc[it][tl] = 0.f;

            #pragma unroll
            for (int tl = 0; tl < 4; tl++) {
                const int t = h2 * 4 + tl;
                if (t < nt) {
                    #pragma unroll
                    for (int j = 0; j < 4; j++) {
                        float4 hv = ((const float4*)hs[t])[j * 32 + lane]; // 1 load -> 4 rows
                        #pragma unroll
                        for (int it = 0; it < 4; it++) {
                            acc[it][tl] += wv[it][j].x * hv.x + wv[it][j].y * hv.y
                                         + wv[it][j].z * hv.z + wv[it][j].w * hv.w;
                        }
                    }
                }
            }

            // Distributing butterfly: token bit1 <- (lane&16), bit0 <- (lane&8);
            // then elementwise reduce over lane bits {4,2,1}.
            #pragma unroll
            for (int it = 0; it < 4; it++) {
                float a0 = acc[it][0], a1 = acc[it][1];
                float a2 = acc[it][2], a3 = acc[it][3];
                {
                    float s0 = (lane & 16) ? a0 : a2, s1 = (lane & 16) ? a1 : a3;
                    float r0 = __shfl_xor_sync(0xffffffffu, s0, 16);
                    float r1 = __shfl_xor_sync(0xffffffffu, s1, 16);
                    a0 = ((lane & 16) ? a2 : a0) + r0;
                    a1 = ((lane & 16) ? a3 : a1) + r1;
                }
                {
                    float s0 = (lane & 8) ? a0 : a1;
                    float r0 = __shfl_xor_sync(0xffffffffu, s0, 8);
                    a0 = ((lane & 8) ? a1 : a0) + r0;
                }
                a0 += __shfl_xor_sync(0xffffffffu, a0, 4);
                a0 += __shfl_xor_sync(0xffffffffu, a0, 2);
                a0 += __shfl_xor_sync(0xffffffffu, a0, 1);

                const int tok = h2 * 4 + (((lane & 16) ? 2 : 0) | ((lane & 8) ? 1 : 0));
                if ((lane & 7) == 0 && tok < nt)
                    out[(size_t)stoks[tok] * H_DIM + row0 + it] = a0 + bias[it];
            }
        }
    }
}

extern "C" void kernel_launch(void* const* d_in, const int* in_sizes, int n_in,
                              void* d_out, int out_size) {
    const float* x        = (const float*)d_in[0];
    const int*   node_ind = (const int*)  d_in[1];
    const float* W1       = (const float*)d_in[2];
    const float* b1       = (const float*)d_in[3];
    const float* W2       = (const float*)d_in[4];
    const float* b2       = (const float*)d_in[5];
    float*       out      = (float*)d_out;

    prep_kernel<<<1, 1024>>>(node_ind);
    layer1_kernel<<<N_NODES * 8 * NC, 256>>>(x, W1, b1);
    layer2_kernel<<<N_NODES * 4 * NC, 256>>>(W2, b2, out);
}